// round 17
// baseline (speedup 1.0000x reference)
#include <cuda_runtime.h>
#include <math.h>

// ---------------------------------------------------------------------------
// MS-SSIM, 5 levels, 16x3x512x512 fp32 (48 planes). ONE launch.
// Ticket scheduler: blocks take a logical id from a global atomic at start.
//   ids [0,12288)      : level-0 tiles (256/image, image-major) + pool pyramid
//   ids [12288,16368)  : levels 1..4 (85/image, image-major); spin-wait until
//                        the image's 256 level-0 blocks are done.
// Deadlock-free regardless of dispatch order: a rest ticket implies all
// level-0 work is held by already-started blocks, which wait on nothing.
// Per-image winner (85th rest finisher) combines into d_total; the 48th
// image-winner writes out and resets all state (graph-replay safe; ticket is
// monotonic mod grid size).
// Compute core (R14-16): no input staging, hblur reads global (L1-hot tile)
// via row-clamped float4; packed f32x2 blur of (x,y) and (x^2+y^2, x*y).
// ---------------------------------------------------------------------------

typedef unsigned long long u64;

__device__ __forceinline__ u64 pack2(float lo, float hi) {
    u64 r; asm("mov.b64 %0,{%1,%2};" : "=l"(r) : "f"(lo), "f"(hi)); return r;
}
__device__ __forceinline__ void unpack2(u64 v, float& lo, float& hi) {
    asm("mov.b64 {%0,%1},%2;" : "=f"(lo), "=f"(hi) : "l"(v));
}
__device__ __forceinline__ u64 fma2(u64 a, u64 b, u64 c) {
    u64 d; asm("fma.rn.f32x2 %0,%1,%2,%3;" : "=l"(d) : "l"(a), "l"(b), "l"(c)); return d;
}
__device__ __forceinline__ u64 mul2(u64 a, u64 b) {
    u64 d; asm("mul.rn.f32x2 %0,%1,%2;" : "=l"(d) : "l"(a), "l"(b)); return d;
}
__device__ __forceinline__ u64 add2(u64 a, u64 b) {
    u64 d; asm("add.rn.f32x2 %0,%1,%2;" : "=l"(d) : "l"(a), "l"(b)); return d;
}
__device__ __forceinline__ float sqrt_fast(float x) {
    float r; asm("sqrt.approx.f32 %0,%1;" : "=f"(r) : "f"(x)); return r;
}

#define TW 32
#define TH 32
#define EH 42
#define EW 42
#define SH_S  33       // stride of h-blurred maps

// gaussian(sigma=1.5, 11 taps), normalized
#define G_0 0.00102838f
#define G_1 0.00759876f
#define G_2 0.03600088f
#define G_3 0.10936090f
#define G_4 0.21300530f
#define G_5 0.26601160f
#define GQ(t) G2c[(t) < 6 ? (t) : 10 - (t)]

#define GRID_TOTAL 16368   // 12288 level0 + 48*85 rest

__device__ __align__(16) float d_Xp[4177920];
__device__ __align__(16) float d_Yp[4177920];
__device__ float d_sums[480];        // [level][img][2]  (winners re-zero)
__device__ unsigned d_l0cnt[48];     // level-0 completion per image
__device__ unsigned d_cnt[48];       // rest completion per image
__device__ unsigned long long d_ticket;  // monotonic; logical id = mod GRID_TOTAL
__device__ float d_total;            // sum of per-image values
__device__ unsigned d_done;          // image winners finished

#define OFF1 0
#define OFF2 3145728
#define OFF3 3932160
#define OFF4 4128768

#define C1V 1e-4f
#define C2V 9e-4f

// core tile worker. POOL => level 0 (H=512, also emits L1..L4 pyramid).
template <bool POOL>
__device__ __forceinline__ void ssim_tile(
    const float* __restrict__ Xi, const float* __restrict__ Yi,
    int H, int level, int img, int bx, int by,
    float* __restrict__ Xp, float* __restrict__ Yp)
{
    __shared__ u64 sMU[EH * SH_S];    // h-blurred (gx,gy)
    __shared__ u64 sSP[EH * SH_S];    // h-blurred (E[xx+yy], E[xy])
    __shared__ u64 sL2[64];
    __shared__ float red[2][8];

    const int W = H;
    const int outH = H - 10;
    const int tx0 = bx * TW;
    const int ty0 = by * TH;
    const int tid = threadIdx.x;

    const u64 G2c[6] = {pack2(G_0,G_0), pack2(G_1,G_1), pack2(G_2,G_2),
                        pack2(G_3,G_3), pack2(G_4,G_4), pack2(G_5,G_5)};

    // ---- fused pool pyramid (level 0 only): L1, L2 (reads global, L1-hot) ---
    if (POOL) {
        const u64 QUARTER = pack2(0.25f, 0.25f);
        const int lane = tid & 31;
        int ph = tid >> 4, pw = tid & 15;
        const float* xr = Xi + (size_t)(ty0 + 2 * ph) * W + tx0 + 2 * pw;
        const float* yr = Yi + (size_t)(ty0 + 2 * ph) * W + tx0 + 2 * pw;
        float2 a0 = __ldg((const float2*)xr);
        float2 a1 = __ldg((const float2*)(xr + W));
        float2 b0 = __ldg((const float2*)yr);
        float2 b1 = __ldg((const float2*)(yr + W));
        float px = 0.25f * ((a0.x + a0.y) + (a1.x + a1.y));
        float py = 0.25f * ((b0.x + b0.y) + (b1.x + b1.y));
        u64 v1 = pack2(px, py);
        {
            size_t po = (size_t)img * 65536 + (size_t)(by * 16 + ph) * 256 + (bx * 16 + pw);
            (Xp + OFF1)[po] = px; (Yp + OFF1)[po] = py;
        }
        u64 s2 = add2(v1, __shfl_xor_sync(0xffffffffu, v1, 1));
        s2 = add2(s2, __shfl_xor_sync(0xffffffffu, s2, 16));
        if ((lane & 17) == 0) {
            u64 v2 = mul2(s2, QUARTER);
            int qh = tid >> 5, qw = lane >> 1;
            float a, b; unpack2(v2, a, b);
            size_t po = (size_t)img * 16384 + (size_t)(by * 8 + qh) * 128 + (bx * 8 + qw);
            (Xp + OFF2)[po] = a; (Yp + OFF2)[po] = b;
            sL2[qh * 8 + qw] = v2;
        }
    }

    // ---- horizontal blur straight from global: 42 rows x 8 groups of 4 ------
    const bool colint = (tx0 + 44 <= W);
    if (colint) {
        auto hblur = [&](int item) {
            int r = item >> 3, c4 = (item & 7) << 2;
            int gr = ty0 + r; if (gr > H - 1) gr = H - 1;
            const float4* xr = (const float4*)(Xi + (size_t)gr * W + tx0 + c4);
            const float4* yr = (const float4*)(Yi + (size_t)gr * W + tx0 + c4);
            float xs[16], ys[16];
#pragma unroll
            for (int j = 0; j < 4; j++) {
                float4 xv = __ldg(xr + j);
                float4 yv = __ldg(yr + j);
                xs[4*j+0] = xv.x; xs[4*j+1] = xv.y; xs[4*j+2] = xv.z; xs[4*j+3] = xv.w;
                ys[4*j+0] = yv.x; ys[4*j+1] = yv.y; ys[4*j+2] = yv.z; ys[4*j+3] = yv.w;
            }
            u64 aMU[4] = {0,0,0,0}, aSP[4] = {0,0,0,0};
#pragma unroll
            for (int k = 0; k < 14; k++) {
                float vx = xs[k], vy = ys[k];
                u64 v  = pack2(vx, vy);
                u64 sp = pack2(fmaf(vx, vx, vy * vy), vx * vy);
#pragma unroll
                for (int q = 0; q < 4; q++) {
                    int t = k - q;
                    if (t >= 0 && t < 11) {
                        aMU[q] = fma2(v,  GQ(t), aMU[q]);
                        aSP[q] = fma2(sp, GQ(t), aSP[q]);
                    }
                }
            }
            int o = r * SH_S + c4;
#pragma unroll
            for (int q = 0; q < 4; q++) {
                sMU[o + q] = aMU[q];
                sSP[o + q] = aSP[q];
            }
        };
        hblur(tid);
        if (tid < EH * 8 - 256) hblur(tid + 256);
    } else {
        auto hblur_g = [&](int item) {
            int r = item >> 3, c4 = (item & 7) << 2;
            int gr = ty0 + r; if (gr > H - 1) gr = H - 1;
            const float* xr = Xi + (size_t)gr * W;
            const float* yr = Yi + (size_t)gr * W;
            u64 aMU[4] = {0,0,0,0}, aSP[4] = {0,0,0,0};
#pragma unroll
            for (int k = 0; k < 14; k++) {
                int gc = tx0 + c4 + k; if (gc > W - 1) gc = W - 1;
                float vx = __ldg(xr + gc), vy = __ldg(yr + gc);
                u64 v  = pack2(vx, vy);
                u64 sp = pack2(fmaf(vx, vx, vy * vy), vx * vy);
#pragma unroll
                for (int q = 0; q < 4; q++) {
                    int t = k - q;
                    if (t >= 0 && t < 11) {
                        aMU[q] = fma2(v,  GQ(t), aMU[q]);
                        aSP[q] = fma2(sp, GQ(t), aSP[q]);
                    }
                }
            }
            int o = r * SH_S + c4;
#pragma unroll
            for (int q = 0; q < 4; q++) {
                sMU[o + q] = aMU[q];
                sSP[o + q] = aSP[q];
            }
        };
        hblur_g(tid);
        if (tid < EH * 8 - 256) hblur_g(tid + 256);
    }
    __syncthreads();

    // ---- pyramid tail: L3 + L4 ------------------------------------------------
    if (POOL && tid < 16) {
        const u64 QUARTER = pack2(0.25f, 0.25f);
        int rh = tid >> 2, rw = tid & 3;
        const u64* q0 = sL2 + (rh * 2) * 8 + rw * 2;
        u64 v3 = mul2(add2(add2(q0[0], q0[1]), add2(q0[8], q0[9])), QUARTER);
        {
            float a, b; unpack2(v3, a, b);
            size_t po = (size_t)img * 4096 + (size_t)(by * 4 + rh) * 64 + (bx * 4 + rw);
            (Xp + OFF3)[po] = a; (Yp + OFF3)[po] = b;
        }
        u64 s4 = add2(v3, __shfl_xor_sync(0xffffu, v3, 1));
        s4 = add2(s4, __shfl_xor_sync(0xffffu, s4, 4));
        if ((tid & 5) == 0) {
            u64 v4 = mul2(s4, QUARTER);
            int sh = tid >> 3, sw = (tid >> 1) & 1;
            float a, b; unpack2(v4, a, b);
            size_t po = (size_t)img * 1024 + (size_t)(by * 2 + sh) * 32 + (bx * 2 + sw);
            (Xp + OFF4)[po] = a; (Yp + OFF4)[po] = b;
        }
    }

    // ---- vertical blur (4 rows per thread) + epilogue ------------------------
    float d_acc = 0.f, cs_acc = 0.f;
    const int ty = tid >> 5, tx = tid & 31;
    const int rbase = ty * 4;
    {
        u64 aMU[4] = {0,0,0,0}, aSP[4] = {0,0,0,0};
#pragma unroll
        for (int k = 0; k < 14; k++) {
            int row = (rbase + k) * SH_S + tx;
            u64 mu = sMU[row];
            u64 sp = sSP[row];
#pragma unroll
            for (int q = 0; q < 4; q++) {
                int t = k - q;
                if (t >= 0 && t < 11) {
                    aMU[q] = fma2(mu, GQ(t), aMU[q]);
                    aSP[q] = fma2(sp, GQ(t), aSP[q]);
                }
            }
        }
        const int ocol = tx0 + tx;
#pragma unroll
        for (int q = 0; q < 4; q++) {
            int orow = ty0 + rbase + q;
            if (orow < outH && ocol < outH) {
                float mu1, mu2, ess, exy;
                unpack2(aMU[q], mu1, mu2);
                unpack2(aSP[q], ess, exy);
                float mu1sq = mu1 * mu1, mu2sq = mu2 * mu2, mu12 = mu1 * mu2;
                float sig_sum = ess - mu1sq - mu2sq;
                float sig12 = exy - mu12;
                float S1 = __fdividef(2.f * mu12 + C1V, mu1sq + mu2sq + C1V);
                float S2 = __fdividef(2.f * sig12 + C2V, sig_sum + C2V);
                float S = fminf(S1 + S2, 2.0f);
                d_acc += sqrt_fast(2.0f - S);
                cs_acc += S2;
            }
        }
    }

    // ---- block reduce + atomic -----------------------------------------------
#pragma unroll
    for (int o = 16; o > 0; o >>= 1) {
        d_acc  += __shfl_down_sync(0xffffffffu, d_acc,  o);
        cs_acc += __shfl_down_sync(0xffffffffu, cs_acc, o);
    }
    if (tx == 0) { red[0][ty] = d_acc; red[1][ty] = cs_acc; }
    __syncthreads();
    if (tid == 0) {
        float ds = 0.f, cs = 0.f;
#pragma unroll
        for (int j = 0; j < 8; j++) { ds += red[0][j]; cs += red[1][j]; }
        atomicAdd(&d_sums[(level * 48 + img) * 2 + 0], ds);
        atomicAdd(&d_sums[(level * 48 + img) * 2 + 1], cs);
    }
}

__global__ void __launch_bounds__(256, 6) ssim_fused_kernel(
    const float* __restrict__ X, const float* __restrict__ Y,
    float* __restrict__ Xp, float* __restrict__ Yp,
    float* __restrict__ out, int out_size)
{
    __shared__ unsigned sL;
    if (threadIdx.x == 0) {
        unsigned long long t = atomicAdd(&d_ticket, 1ULL);
        sL = (unsigned)(t % (unsigned long long)GRID_TOTAL);
    }
    __syncthreads();
    const unsigned L = sL;

    if (L < 12288u) {
        // ---- level 0 tile ----
        int img = L >> 8;
        int t = L & 255;
        int by = t >> 4, bx = t & 15;
        const float* Xi = X + (size_t)img * 262144;
        const float* Yi = Y + (size_t)img * 262144;
        ssim_tile<true>(Xi, Yi, 512, 0, img, bx, by, Xp, Yp);
        if (threadIdx.x == 0) {
            __threadfence();
            atomicAdd(&d_l0cnt[img], 1u);
        }
        return;
    }

    // ---- rest tile (levels 1..4) ----
    unsigned r = L - 12288u;
    int img = r / 85u;
    int u = r % 85u;

    // wait for this image's level-0 blocks (deadlock-free: ticket order
    // guarantees all level-0 work is held by already-started blocks)
    if (threadIdx.x == 0) {
        while (atomicAdd(&d_l0cnt[img], 0u) < 256u) __nanosleep(200);
    }
    __syncthreads();

    int level, H, nt, off, uu;
    if (u < 64)      { level = 1; H = 256; nt = 8; off = OFF1; uu = u; }
    else if (u < 80) { level = 2; H = 128; nt = 4; off = OFF2; uu = u - 64; }
    else if (u < 84) { level = 3; H = 64;  nt = 2; off = OFF3; uu = u - 80; }
    else             { level = 4; H = 32;  nt = 1; off = OFF4; uu = 0; }
    int by = uu / nt, bx = uu - by * nt;
    const float* Xi = Xp + off + (size_t)img * H * H;
    const float* Yi = Yp + off + (size_t)img * H * H;
    ssim_tile<false>(Xi, Yi, H, level, img, bx, by, nullptr, nullptr);

    // completion protocol: 85 rest blocks per image; last one combines.
    if (threadIdx.x == 0) {
        __threadfence();
        unsigned old = atomicAdd(&d_cnt[img], 1u);
        if (old == 84u) {
            // read sums through L2 (atomic RMW dodges stale L1 lines)
            float cs0 = atomicAdd(&d_sums[(0 * 48 + img) * 2 + 1], 0.f);
            float cs1 = atomicAdd(&d_sums[(1 * 48 + img) * 2 + 1], 0.f);
            float cs2 = atomicAdd(&d_sums[(2 * 48 + img) * 2 + 1], 0.f);
            float cs3 = atomicAdd(&d_sums[(3 * 48 + img) * 2 + 1], 0.f);
            float ds4 = atomicAdd(&d_sums[(4 * 48 + img) * 2 + 0], 0.f);
            float v = 1.f;
            v *= __powf(fmaxf(cs0 * (1.f / 252004.f), 0.f), 0.0448f);
            v *= __powf(fmaxf(cs1 * (1.f / 60516.f),  0.f), 0.2856f);
            v *= __powf(fmaxf(cs2 * (1.f / 13924.f),  0.f), 0.3001f);
            v *= __powf(fmaxf(cs3 * (1.f / 2916.f),   0.f), 0.2363f);
            v *= __powf(fmaxf(ds4 * (1.f / 484.f),    0.f), 0.1333f);
            atomicAdd(&d_total, v * (1.0f / 48.0f));
            // reset this image's state for the next launch/replay
#pragma unroll
            for (int l = 0; l < 5; l++) {
                atomicExch(&d_sums[(l * 48 + img) * 2 + 0], 0.f);
                atomicExch(&d_sums[(l * 48 + img) * 2 + 1], 0.f);
            }
            atomicExch(&d_cnt[img], 0u);
            atomicExch(&d_l0cnt[img], 0u);
            __threadfence();
            unsigned od = atomicAdd(&d_done, 1u);
            if (od == 47u) {
                float tot = atomicAdd(&d_total, 0.f);
                for (int k = 0; k < out_size; k++) out[k] = tot;
                atomicExch(&d_total, 0.f);
                atomicExch(&d_done, 0u);
            }
        }
    }
}

extern "C" void kernel_launch(void* const* d_in, const int* in_sizes, int n_in,
                              void* d_out, int out_size)
{
    const float* X = (const float*)d_in[0];
    const float* Y = (const float*)d_in[1];
    float* out = (float*)d_out;

    float *Xp = nullptr, *Yp = nullptr;
    cudaGetSymbolAddress((void**)&Xp, d_Xp);
    cudaGetSymbolAddress((void**)&Yp, d_Yp);

    ssim_fused_kernel<<<GRID_TOTAL, 256>>>(X, Y, Xp, Yp, out, out_size);
}